// round 13
// baseline (speedup 1.0000x reference)
#include <cuda_runtime.h>
#include <math.h>

// Problem constants
#define NN 16384
#define NB 64
#define NVOCAB 100
#define NL0 128
#define NH 64

// Scratch (__device__ globals — no allocation allowed)
__device__ float g_px[NN], g_py[NN], g_pz[NN], g_sq[NN];
__device__ int2  g_band[NN];          // (lo, hi) packed: one 8B load per thread
__device__ float g_table[NVOCAB];

// ---------------------------------------------------------------------------
// Kernel A: fused prep + MLP table.  (R9-proven version.)
//   blocks [0, 64):    prep — SoA pos split, sq, same-batch band via binary
//                      search on sorted batch (int32/int64 auto-detected).
//   blocks [64, 164):  MLP collapsed to 100-entry vocab table.
// ---------------------------------------------------------------------------
__global__ void fused_prep_mlp(const void* __restrict__ batch_raw,
                               const float* __restrict__ pos,
                               const float* __restrict__ emb,
                               const float* __restrict__ w1,
                               const float* __restrict__ b1,
                               const float* __restrict__ w2,
                               const float* __restrict__ b2) {
    if (blockIdx.x < 64) {
        // ---- prep ----
        int i = blockIdx.x * 256 + threadIdx.x;

        float x = pos[3 * i + 0];
        float y = pos[3 * i + 1];
        float z = pos[3 * i + 2];
        g_px[i] = x; g_py[i] = y; g_pz[i] = z;
        // sq: separate rounds, no fma contraction (matches XLA mul+add)
        g_sq[i] = __fadd_rn(__fadd_rn(__fmul_rn(x, x), __fmul_rn(y, y)),
                            __fmul_rn(z, z));

        // Detect batch dtype: int32 layout -> word [NN-1] = max batch (~63);
        // int64 LE layout -> word [NN-1] is a high word = 0.
        const int* w32 = (const int*)batch_raw;
        bool is32 = (w32[NN - 1] != 0);

        long long bi = is32 ? (long long)w32[i]
                            : ((const long long*)batch_raw)[i];

        // lower_bound
        int lo = 0, hi = NN;
        while (lo < hi) {
            int m = (lo + hi) >> 1;
            long long bm = is32 ? (long long)w32[m]
                                : ((const long long*)batch_raw)[m];
            if (bm < bi) lo = m + 1; else hi = m;
        }
        int lb = lo;
        // upper_bound
        lo = 0; hi = NN;
        while (lo < hi) {
            int m = (lo + hi) >> 1;
            long long bm = is32 ? (long long)w32[m]
                                : ((const long long*)batch_raw)[m];
            if (bm <= bi) lo = m + 1; else hi = m;
        }
        g_band[i] = make_int2(lb, lo);
    } else {
        // ---- MLP table: out depends on z only through emb[z]; 100 rows ----
        __shared__ float sh[NH];
        int v = blockIdx.x - 64;
        int j = threadIdx.x;

        if (j < NH) {
            const float* e = emb + (size_t)v * NL0;
            float acc = b1[j];
#pragma unroll 8
            for (int k = 0; k < NL0; k++)
                acc = fmaf(e[k], w1[k * NH + j], acc);
            // silu(x) = x * sigmoid(x)
            float s = 1.0f / (1.0f + expf(-acc));
            sh[j] = (acc * s) * w2[j];
        }
        __syncthreads();
        if (j == 0) {
            float o = 0.0f;
            for (int k = 0; k < NH; k++) o += sh[k];
            g_table[v] = o + b2[0];
        }
    }
}

// ---------------------------------------------------------------------------
// Kernel B: adjacency mask (HBM-write bound) + gather epilogue.
//   blocks [0, 64) additionally write out[i] = table[z[i]] first.
//
// Mapping: block b -> row (b >> 1), half (b & 1); thread handles chunks
// tid + k*256, k=0..7 (lane-contiguous -> full coalescing). Row state
// hoisted; per-chunk fine check keeps loads/FMA off the stream for ~99% of
// chunks (R11: removing it cost DRAM% 90->63, wall +40us).
//
// Store cache-op A/B history (wall clock, graph replay — NOT single-pass
// ncu, which inverted the stcs/wb ordering):
//   plain write-back: 180.8us | __stcs evict-first: 151.2us | __stwt: THIS RUN
// Write-through never allocates the L2 line; since the stcs win came from
// reducing L2 write-back involvement, stwt probes the far end of that axis.
// No __launch_bounds__: R12 showed occ 60->82% was DRAM-neutral; R9's
// 40-reg compile is the fastest measured.
//
// In-band: d2 = (sq_i + sq_j) - 2*dot (ascending fma chain) — exact match
// of the reference's sq[:,None]+sq[None,:]-2*(pos@pos.T) rounding.
// ---------------------------------------------------------------------------
__global__ void adj_gather_kernel(const int* __restrict__ z,
                                  float* __restrict__ out,
                                  float4* __restrict__ adj) {
    if (blockIdx.x < 64) {
        int idx = blockIdx.x * 256 + threadIdx.x;
        out[idx] = g_table[z[idx]];
    }

    int row  = blockIdx.x >> 1;
    int half = blockIdx.x & 1;
    int2 band = g_band[row];
    int lo = band.x, hi = band.y;

    unsigned cbase = (unsigned)row * 4096u + (unsigned)half * 2048u; // chunk base
    int jbase = half * 8192;                                        // element base

    const float4 zero = make_float4(0.f, 0.f, 0.f, 0.f);

    // No overlap between this half-row [jbase, jbase+8192) and [lo, hi)?
    if (jbase + 8192 <= lo || jbase >= hi) {
        // Pure zero-fill fast path
#pragma unroll
        for (int k = 0; k < 8; k++)
            __stwt(&adj[cbase + threadIdx.x + k * 256], zero);
    } else {
        float xi = g_px[row], yi = g_py[row], zi = g_pz[row], sqi = g_sq[row];
#pragma unroll
        for (int k = 0; k < 8; k++) {
            int c  = threadIdx.x + k * 256;      // chunk within half-row
            int j0 = jbase + (c << 2);           // first element of chunk
            float4 v = zero;
            if (j0 + 3 >= lo && j0 < hi) {       // fine check: ~99% skip
                float r[4];
#pragma unroll
                for (int e = 0; e < 4; e++) {
                    int j = j0 + e;
                    float val = 0.0f;
                    if (j >= lo && j < hi && j != row) {
                        float dot = fmaf(zi, g_pz[j],
                                    fmaf(yi, g_py[j],
                                         __fmul_rn(xi, g_px[j])));
                        float d2 = __fsub_rn(__fadd_rn(sqi, g_sq[j]),
                                             __fmul_rn(2.0f, dot));
                        val = (d2 < 64.0f) ? 1.0f : 0.0f;
                    }
                    r[e] = val;
                }
                v = make_float4(r[0], r[1], r[2], r[3]);
            }
            __stwt(&adj[cbase + c], v);
        }
    }
}

// ---------------------------------------------------------------------------
extern "C" void kernel_launch(void* const* d_in, const int* in_sizes, int n_in,
                              void* d_out, int out_size) {
    const int*   z     = (const int*)d_in[0];
    const void*  batch = d_in[1];           // int32 or int64, device-detected
    const float* pos   = (const float*)d_in[2];
    const float* emb   = (const float*)d_in[3];
    const float* w1    = (const float*)d_in[4];
    const float* b1    = (const float*)d_in[5];
    const float* w2    = (const float*)d_in[6];
    const float* b2    = (const float*)d_in[7];
    float* out = (float*)d_out;

    fused_prep_mlp<<<164, 256>>>(batch, pos, emb, w1, b1, w2, b2);
    adj_gather_kernel<<<32768, 256>>>(z, out, (float4*)(out + NN));
}